// round 7
// baseline (speedup 1.0000x reference)
#include <cuda_runtime.h>
#include <math.h>

#define C_DIM    256
#define H_DIM    8
#define B_GRAPHS 2048
#define NPG_     128
#define N_NODES  (B_GRAPHS * NPG_)
#define EPS_     1e-5f
#define ATTN_SCALE 0.17677669529663687f   /* 1/sqrt(32) */

// ---------------- scratch (device globals; no allocation allowed) ----------------
__device__ float g_h1[(size_t)N_NODES * C_DIM];   // 256 MB scratch for h1
__device__ float g_sum[C_DIM];
__device__ float g_sumsq[C_DIM];
__device__ float g_na[C_DIM];       // gamma*rsqrt(var+eps)
__device__ float g_nd[C_DIM];       // beta - mu*na
__device__ float g_w16[16 * C_DIM]; // e<8: scale*wk_eff[h][:], e>=8: wv_eff[h][:]
__device__ float g_b16[16];
__device__ float g_c0;              // Wr.bo + br

// ---------------- f32x2 packed-FMA helpers --------------------------------------
__device__ __forceinline__ unsigned long long f2pack(float lo, float hi) {
    unsigned long long r;
    asm("mov.b64 %0, {%1, %2};" : "=l"(r) : "f"(lo), "f"(hi));
    return r;
}
__device__ __forceinline__ void ffma2(unsigned long long& d,
                                      unsigned long long a, unsigned long long b) {
    asm("fma.rn.f32x2 %0, %1, %2, %0;" : "+l"(d) : "l"(a), "l"(b));
}
__device__ __forceinline__ void f2unpack(unsigned long long v, float& lo, float& hi) {
    asm("mov.b64 {%0, %1}, %2;" : "=f"(lo), "=f"(hi) : "l"(v));
}

// ---------------- kernel Z: zero stats ------------------------------------------
__global__ void kZero() {
    int t = threadIdx.x;
    if (t < C_DIM) { g_sum[t] = 0.f; g_sumsq[t] = 0.f; }
}

// ---------------- kernel A: h1 = x @ W1^T + b1, + column sum/sumsq ---------------
// grid 2048, block 512.  Tile 128m x 256n, BK=16.
// Warp w owns rows [w*8, w*8+8) as 4 f32x2 m-pairs; lane l owns cols {l+32q}.
__global__ void __launch_bounds__(512, 1)
kA(const float* __restrict__ x, const float* __restrict__ W1, const float* __restrict__ b1)
{
    __shared__ __align__(16) float xst[2][16][128];   // [k][m]  (k-major A)
    __shared__ __align__(16) float ws[2][16][256];    // [k][n]  (k-major B)
    __shared__ float csum[256];
    __shared__ float csq[256];

    const int t = threadIdx.x;
    const int w = t >> 5, l = t & 31;
    const int m0 = w * 8;
    const size_t rowbase = (size_t)blockIdx.x * 128;

    if (t < 256) { csum[t] = 0.f; csq[t] = 0.f; }

    unsigned long long acc[4][8];
#pragma unroll
    for (int p = 0; p < 4; ++p)
#pragma unroll
        for (int q = 0; q < 8; ++q) acc[p][q] = 0ULL;

    // prologue: chunk 0
    {
        int m  = t >> 2;
        int kq = (t & 3) * 4;
        float4 vx = *(const float4*)&x[(rowbase + m) * 256 + kq];
        xst[0][kq + 0][m] = vx.x; xst[0][kq + 1][m] = vx.y;
        xst[0][kq + 2][m] = vx.z; xst[0][kq + 3][m] = vx.w;
#pragma unroll
        for (int i = 0; i < 2; ++i) {
            int f = t + 512 * i;
            int n = f >> 2;
            int k2 = (f & 3) * 4;
            float4 vw = *(const float4*)&W1[(size_t)n * 256 + k2];
            ws[0][k2 + 0][n] = vw.x; ws[0][k2 + 1][n] = vw.y;
            ws[0][k2 + 2][n] = vw.z; ws[0][k2 + 3][n] = vw.w;
        }
    }
    __syncthreads();

    float4 pfx;
    float4 pfw[2];
    for (int ch = 0; ch < 16; ++ch) {
        const int cur = ch & 1;
        if (ch < 15) {
            const int kc = (ch + 1) * 16;
            {
                int m  = t >> 2;
                int kq = (t & 3) * 4;
                pfx = *(const float4*)&x[(rowbase + m) * 256 + kc + kq];
            }
#pragma unroll
            for (int i = 0; i < 2; ++i) {
                int f = t + 512 * i;
                int n = f >> 2;
                int k2 = (f & 3) * 4;
                pfw[i] = *(const float4*)&W1[(size_t)n * 256 + kc + k2];
            }
        }
#pragma unroll
        for (int kk = 0; kk < 16; ++kk) {
            unsigned long long av[4];
            const unsigned long long* xrow =
                (const unsigned long long*)&xst[cur][kk][m0];
#pragma unroll
            for (int p = 0; p < 4; ++p) av[p] = xrow[p];
            unsigned long long bv[8];
#pragma unroll
            for (int q = 0; q < 8; ++q) {
                float b = ws[cur][kk][l + 32 * q];
                bv[q] = f2pack(b, b);
            }
#pragma unroll
            for (int p = 0; p < 4; ++p)
#pragma unroll
                for (int q = 0; q < 8; ++q) ffma2(acc[p][q], av[p], bv[q]);
        }
        __syncthreads();
        if (ch < 15) {
            const int nxt = cur ^ 1;
            {
                int m  = t >> 2;
                int kq = (t & 3) * 4;
                xst[nxt][kq + 0][m] = pfx.x; xst[nxt][kq + 1][m] = pfx.y;
                xst[nxt][kq + 2][m] = pfx.z; xst[nxt][kq + 3][m] = pfx.w;
            }
#pragma unroll
            for (int i = 0; i < 2; ++i) {
                int f = t + 512 * i;
                int n = f >> 2;
                int k2 = (f & 3) * 4;
                ws[nxt][k2 + 0][n] = pfw[i].x; ws[nxt][k2 + 1][n] = pfw[i].y;
                ws[nxt][k2 + 2][n] = pfw[i].z; ws[nxt][k2 + 3][n] = pfw[i].w;
            }
            __syncthreads();
        }
    }

    // epilogue: +b1, store h1, column sums
    float b1v[8];
#pragma unroll
    for (int q = 0; q < 8; ++q) b1v[q] = b1[l + 32 * q];

    float cs[8], cq[8];
#pragma unroll
    for (int q = 0; q < 8; ++q) { cs[q] = 0.f; cq[q] = 0.f; }

#pragma unroll
    for (int p = 0; p < 4; ++p) {
        size_t r0 = (rowbase + m0 + 2 * p) * 256;
#pragma unroll
        for (int q = 0; q < 8; ++q) {
            float v0, v1;
            f2unpack(acc[p][q], v0, v1);
            v0 += b1v[q]; v1 += b1v[q];
            int n = l + 32 * q;
            g_h1[r0 + n]       = v0;
            g_h1[r0 + 256 + n] = v1;
            cs[q] += v0 + v1;
            cq[q] += v0 * v0 + v1 * v1;
        }
    }

#pragma unroll
    for (int q = 0; q < 8; ++q) {
        atomicAdd(&csum[l + 32 * q], cs[q]);
        atomicAdd(&csq[l + 32 * q],  cq[q]);
    }
    __syncthreads();
    if (t < 256) {
        atomicAdd(&g_sum[t],   csum[t]);
        atomicAdd(&g_sumsq[t], csq[t]);
    }
}

// ---------------- kernel B: finalize stats + fold small weights ------------------
__global__ void kB(const float* __restrict__ gamma, const float* __restrict__ beta,
                   const float* __restrict__ Wq, const float* __restrict__ bq,
                   const float* __restrict__ Wk, const float* __restrict__ bk,
                   const float* __restrict__ Wv, const float* __restrict__ bv,
                   const float* __restrict__ Wo, const float* __restrict__ bo,
                   const float* __restrict__ Wr, const float* __restrict__ br)
{
    __shared__ float qv[256], we[256], wrs[256];
    const int t = threadIdx.x;
    const float invN = 1.0f / (float)N_NODES;

    float mean = g_sum[t] * invN;
    float var  = g_sumsq[t] * invN - mean * mean;
    float rs   = rsqrtf(var + EPS_);
    float na   = gamma[t] * rs;
    g_na[t] = na;
    g_nd[t] = beta[t] - mean * na;

    float s = bq[t];
    for (int j = 0; j < 256; ++j) s += Wq[(size_t)t * 256 + j];
    qv[t]  = s;
    wrs[t] = Wr[t];
    __syncthreads();

    float e = 0.f;
    for (int j = 0; j < 256; ++j) e += wrs[j] * Wo[(size_t)j * 256 + t];
    we[t] = e;
    __syncthreads();

    for (int h = 0; h < 8; ++h) {
        float wk = 0.f, wv_ = 0.f;
        for (int d = 0; d < 32; ++d) {
            int c = h * 32 + d;
            wk  += qv[c] * Wk[(size_t)c * 256 + t];
            wv_ += we[c] * Wv[(size_t)c * 256 + t];
        }
        g_w16[h * 256 + t]       = wk * ATTN_SCALE;
        g_w16[(8 + h) * 256 + t] = wv_;
    }
    if (t < 8) {
        float bl = 0.f, bs = 0.f;
        for (int d = 0; d < 32; ++d) {
            int c = t * 32 + d;
            bl += qv[c] * bk[c];
            bs += we[c] * bv[c];
        }
        g_b16[t]     = bl * ATTN_SCALE;
        g_b16[8 + t] = bs;
    }
    if (t == 0) {
        float c0 = br[0];
        for (int j = 0; j < 256; ++j) c0 += wrs[j] * bo[j];
        g_c0 = c0;
    }
}

// ---------------- kernel C: per-group norm/relu/GEMM2/attn/out -------------------
// smem (floats):
#define YSTR_    130                              // y^T [k][m], padded
#define YS_OFF   0                                // 256*130 = 33280 (reused as h2[m][260])
#define H2STR_   260
#define WS2_OFF  33280                            // 2*16*256 = 8192
#define W16_OFF  (WS2_OFF + 8192)                 // 41472 ; 16 rows stride 260
#define W16STR_  260
#define LG_OFF   (W16_OFF + 16 * W16STR_)         // 45632 ; 128 rows stride 17
#define LGSTR_   17
#define HR_OFF   (LG_OFF + 128 * LGSTR_)          // 47808
#define NA_OFF   (HR_OFF + 8)                     // 47816 (16B aligned)
#define ND_OFF   (NA_OFF + 256)
#define SMC_FLOATS (ND_OFF + 256)                 // 48328 floats = 193312 B

__global__ void __launch_bounds__(512, 1)
kC(const float* __restrict__ W2, const float* __restrict__ b2, float* __restrict__ out)
{
    extern __shared__ float sm[];
    const int t = threadIdx.x;
    const int w = t >> 5, l = t & 31;
    const int m0 = w * 8;
    const int g = blockIdx.x;
    const float* h1 = g_h1 + (size_t)g * (128 * 256);

    if (t < 256) { sm[NA_OFF + t] = g_na[t]; sm[ND_OFF + t] = g_nd[t]; }
    __syncthreads();

    // phase 1: y = relu(na*h1 + nd) -> yst[k][m]; stage w16; W2 chunk 0
#pragma unroll
    for (int i = 0; i < 16; ++i) {
        int f  = t + 512 * i;
        int m  = f >> 6;
        int c4 = (f & 63) * 4;
        float4 v = *(const float4*)&h1[(size_t)m * 256 + c4];
        float4 a = *(const float4*)&sm[NA_OFF + c4];
        float4 d = *(const float4*)&sm[ND_OFF + c4];
        v.x = fmaxf(fmaf(v.x, a.x, d.x), 0.f);
        v.y = fmaxf(fmaf(v.y, a.y, d.y), 0.f);
        v.z = fmaxf(fmaf(v.z, a.z, d.z), 0.f);
        v.w = fmaxf(fmaf(v.w, a.w, d.w), 0.f);
        sm[YS_OFF + (c4 + 0) * YSTR_ + m] = v.x;
        sm[YS_OFF + (c4 + 1) * YSTR_ + m] = v.y;
        sm[YS_OFF + (c4 + 2) * YSTR_ + m] = v.z;
        sm[YS_OFF + (c4 + 3) * YSTR_ + m] = v.w;
    }
#pragma unroll
    for (int i = 0; i < 2; ++i) {
        int f  = t + 512 * i;
        int e  = f >> 6;
        int c4 = (f & 63) * 4;
        float4 v = *(const float4*)&g_w16[e * 256 + c4];
        *(float4*)&sm[W16_OFF + e * W16STR_ + c4] = v;
    }
#pragma unroll
    for (int i = 0; i < 2; ++i) {
        int f = t + 512 * i;
        int n = f >> 2;
        int k2 = (f & 3) * 4;
        float4 vw = *(const float4*)&W2[(size_t)n * 256 + k2];
        sm[WS2_OFF + (k2 + 0) * 256 + n] = vw.x;
        sm[WS2_OFF + (k2 + 1) * 256 + n] = vw.y;
        sm[WS2_OFF + (k2 + 2) * 256 + n] = vw.z;
        sm[WS2_OFF + (k2 + 3) * 256 + n] = vw.w;
    }
    __syncthreads();

    // GEMM2 main loop
    unsigned long long acc[4][8];
#pragma unroll
    for (int p = 0; p < 4; ++p)
#pragma unroll
        for (int q = 0; q < 8; ++q) acc[p][q] = 0ULL;

    float4 pfw[2];
    for (int ch = 0; ch < 16; ++ch) {
        const int cur = ch & 1;
        if (ch < 15) {
            const int kc = (ch + 1) * 16;
#pragma unroll
            for (int i = 0; i < 2; ++i) {
                int f = t + 512 * i;
                int n = f >> 2;
                int k2 = (f & 3) * 4;
                pfw[i] = *(const float4*)&W2[(size_t)n * 256 + kc + k2];
            }
        }
#pragma unroll
        for (int kk = 0; kk < 16; ++kk) {
            const int k = ch * 16 + kk;
            unsigned long long av[4];
            const unsigned long long* yrow =
                (const unsigned long long*)&sm[YS_OFF + k * YSTR_ + m0];
#pragma unroll
            for (int p = 0; p < 4; ++p) av[p] = yrow[p];
            unsigned long long bv[8];
#pragma unroll
            for (int q = 0; q < 8; ++q) {
                float b = sm[WS2_OFF + cur * 4096 + kk * 256 + l + 32 * q];
                bv[q] = f2pack(b, b);
            }
#pragma unroll
            for (int p = 0; p < 4; ++p)
#pragma unroll
                for (int q = 0; q < 8; ++q) ffma2(acc[p][q], av[p], bv[q]);
        }
        __syncthreads();
        if (ch < 15) {
            const int nxt = cur ^ 1;
#pragma unroll
            for (int i = 0; i < 2; ++i) {
                int f = t + 512 * i;
                int n = f >> 2;
                int k2 = (f & 3) * 4;
                sm[WS2_OFF + nxt * 4096 + (k2 + 0) * 256 + n] = pfw[i].x;
                sm[WS2_OFF + nxt * 4096 + (k2 + 1) * 256 + n] = pfw[i].y;
                sm[WS2_OFF + nxt * 4096 + (k2 + 2) * 256 + n] = pfw[i].z;
                sm[WS2_OFF + nxt * 4096 + (k2 + 3) * 256 + n] = pfw[i].w;
            }
            __syncthreads();
        }
    }

    // h2 = acc + b2 -> smem [m][260] (overwrites yst; all reads of y done)
    {
        float b2v[8];
#pragma unroll
        for (int q = 0; q < 8; ++q) b2v[q] = b2[l + 32 * q];
#pragma unroll
        for (int p = 0; p < 4; ++p) {
            int r0 = YS_OFF + (m0 + 2 * p) * H2STR_;
#pragma unroll
            for (int q = 0; q < 8; ++q) {
                float v0, v1;
                f2unpack(acc[p][q], v0, v1);
                int n = l + 32 * q;
                sm[r0 + n]          = v0 + b2v[q];
                sm[r0 + H2STR_ + n] = v1 + b2v[q];
            }
        }
    }
    __syncthreads();

    // phase 4: out16[n][e] = h2[n,:] . w16[e,:] + b16[e]  (packed f32x2)
    {
        const int e  = t & 15;
        const int nb = t >> 4;            // 0..31
        unsigned long long a2[4];
#pragma unroll
        for (int i = 0; i < 4; ++i) a2[i] = 0ULL;
        const float* wrow = &sm[W16_OFF + e * W16STR_];
#pragma unroll 4
        for (int k4 = 0; k4 < 64; ++k4) {
            ulonglong2 wv = *(const ulonglong2*)&wrow[k4 * 4];
#pragma unroll
            for (int i = 0; i < 4; ++i) {
                ulonglong2 hv =
                    *(const ulonglong2*)&sm[YS_OFF + (nb + 32 * i) * H2STR_ + k4 * 4];
                ffma2(a2[i], hv.x, wv.x);
                ffma2(a2[i], hv.y, wv.y);
            }
        }
        float bb = g_b16[e];
#pragma unroll
        for (int i = 0; i < 4; ++i) {
            float lo, hi;
            f2unpack(a2[i], lo, hi);
            sm[LG_OFF + (nb + 32 * i) * LGSTR_ + e] = lo + hi + bb;
        }
    }
    __syncthreads();

    // phase 5: per-head softmax over 128 nodes + weighted sum
    {
        const int wh   = t >> 5;
        const int lane = t & 31;
        if (wh < 8) {
            float lv[4];
#pragma unroll
            for (int i = 0; i < 4; ++i)
                lv[i] = sm[LG_OFF + (lane + 32 * i) * LGSTR_ + wh];
            float m = fmaxf(fmaxf(lv[0], lv[1]), fmaxf(lv[2], lv[3]));
#pragma unroll
            for (int o = 16; o > 0; o >>= 1)
                m = fmaxf(m, __shfl_xor_sync(0xffffffffu, m, o));
            float ps = 0.f, pv = 0.f;
#pragma unroll
            for (int i = 0; i < 4; ++i) {
                float p = __expf(lv[i] - m);
                ps += p;
                pv += p * sm[LG_OFF + (lane + 32 * i) * LGSTR_ + 8 + wh];
            }
#pragma unroll
            for (int o = 16; o > 0; o >>= 1) {
                ps += __shfl_xor_sync(0xffffffffu, ps, o);
                pv += __shfl_xor_sync(0xffffffffu, pv, o);
            }
            if (lane == 0) sm[HR_OFF + wh] = pv / ps;
        }
    }
    __syncthreads();
    if (t == 0) {
        float r = g_c0;
#pragma unroll
        for (int h = 0; h < 8; ++h) r += sm[HR_OFF + h];
        out[g] = tanhf(r);
    }
}

// ---------------- launch ---------------------------------------------------------
extern "C" void kernel_launch(void* const* d_in, const int* in_sizes, int n_in,
                              void* d_out, int out_size)
{
    const int base = n_in - 16;
    const float* x     = (const float*)d_in[0];
    const float* W1    = (const float*)d_in[base + 0];
    const float* b1    = (const float*)d_in[base + 1];
    const float* gamma = (const float*)d_in[base + 2];
    const float* beta  = (const float*)d_in[base + 3];
    const float* W2    = (const float*)d_in[base + 4];
    const float* b2    = (const float*)d_in[base + 5];
    const float* Wq    = (const float*)d_in[base + 6];
    const float* bq    = (const float*)d_in[base + 7];
    const float* Wk    = (const float*)d_in[base + 8];
    const float* bk    = (const float*)d_in[base + 9];
    const float* Wv    = (const float*)d_in[base + 10];
    const float* bv    = (const float*)d_in[base + 11];
    const float* Wo    = (const float*)d_in[base + 12];
    const float* bo    = (const float*)d_in[base + 13];
    const float* Wr    = (const float*)d_in[base + 14];
    const float* br    = (const float*)d_in[base + 15];

    kZero<<<1, 256>>>();
    kA<<<B_GRAPHS, 512>>>(x, W1, b1);
    kB<<<1, 256>>>(gamma, beta, Wq, bq, Wk, bk, Wv, bv, Wo, bo, Wr, br);

    const size_t shc = (size_t)SMC_FLOATS * sizeof(float);
    cudaFuncSetAttribute((const void*)kC,
                         cudaFuncAttributeMaxDynamicSharedMemorySize, (int)shc);
    kC<<<B_GRAPHS, 512, shc>>>(W2, b2, (float*)d_out);
}

// round 9
// speedup vs baseline: 1.6202x; 1.6202x over previous
#include <cuda_runtime.h>
#include <math.h>

#define C_DIM    256
#define H_DIM    8
#define B_GRAPHS 2048
#define NPG_     128
#define N_NODES  (B_GRAPHS * NPG_)
#define EPS_     1e-5f
#define ATTN_SCALE 0.17677669529663687f   /* 1/sqrt(32) */

// ---------------- scratch (device globals; no allocation allowed) ----------------
__device__ float g_h1[(size_t)N_NODES * C_DIM];   // 256 MB scratch for h1
__device__ float g_sum[C_DIM];
__device__ float g_sumsq[C_DIM];
__device__ float g_na[C_DIM];       // gamma*rsqrt(var+eps)
__device__ float g_nd[C_DIM];       // beta - mu*na
__device__ float g_w16[16 * C_DIM]; // e<8: scale*wk_eff[h][:], e>=8: wv_eff[h][:]
__device__ float g_b16[16];
__device__ float g_c0;              // Wr.bo + br

// ---------------- f32x2 packed-FMA helpers --------------------------------------
__device__ __forceinline__ unsigned long long f2pack(float lo, float hi) {
    unsigned long long r;
    asm("mov.b64 %0, {%1, %2};" : "=l"(r) : "f"(lo), "f"(hi));
    return r;
}
__device__ __forceinline__ void ffma2(unsigned long long& d,
                                      unsigned long long a, unsigned long long b) {
    asm("fma.rn.f32x2 %0, %1, %2, %0;" : "+l"(d) : "l"(a), "l"(b));
}
__device__ __forceinline__ void f2unpack(unsigned long long v, float& lo, float& hi) {
    asm("mov.b64 {%0, %1}, %2;" : "=f"(lo), "=f"(hi) : "l"(v));
}

// ---------------- kernel Z: zero stats ------------------------------------------
__global__ void kZero() {
    int t = threadIdx.x;
    if (t < C_DIM) { g_sum[t] = 0.f; g_sumsq[t] = 0.f; }
}

// ---------------- kernel A: h1 = x @ W1^T + b1, + column sum/sumsq ---------------
// grid 2048, block 512.  Tile 128m x 256n, BK=16.
// Warp w owns rows [w*8, w*8+8) as 4 f32x2 m-pairs; lane l owns cols {l+32q}.
__global__ void __launch_bounds__(512, 1)
kA(const float* __restrict__ x, const float* __restrict__ W1, const float* __restrict__ b1)
{
    __shared__ __align__(16) float xst[2][16][128];   // [k][m]  (k-major A)
    __shared__ __align__(16) float ws[2][16][256];    // [k][n]  (k-major B)
    __shared__ float csum[256];
    __shared__ float csq[256];

    const int t = threadIdx.x;
    const int w = t >> 5, l = t & 31;
    const int m0 = w * 8;
    const size_t rowbase = (size_t)blockIdx.x * 128;

    if (t < 256) { csum[t] = 0.f; csq[t] = 0.f; }

    unsigned long long acc[4][8];
#pragma unroll
    for (int p = 0; p < 4; ++p)
#pragma unroll
        for (int q = 0; q < 8; ++q) acc[p][q] = 0ULL;

    // prologue: chunk 0
    {
        int m  = t >> 2;
        int kq = (t & 3) * 4;
        float4 vx = *(const float4*)&x[(rowbase + m) * 256 + kq];
        xst[0][kq + 0][m] = vx.x; xst[0][kq + 1][m] = vx.y;
        xst[0][kq + 2][m] = vx.z; xst[0][kq + 3][m] = vx.w;
#pragma unroll
        for (int i = 0; i < 2; ++i) {
            int f = t + 512 * i;
            int n = f >> 2;
            int k2 = (f & 3) * 4;
            float4 vw = *(const float4*)&W1[(size_t)n * 256 + k2];
            ws[0][k2 + 0][n] = vw.x; ws[0][k2 + 1][n] = vw.y;
            ws[0][k2 + 2][n] = vw.z; ws[0][k2 + 3][n] = vw.w;
        }
    }
    __syncthreads();

    float4 pfx;
    float4 pfw[2];
    for (int ch = 0; ch < 16; ++ch) {
        const int cur = ch & 1;
        if (ch < 15) {
            const int kc = (ch + 1) * 16;
            {
                int m  = t >> 2;
                int kq = (t & 3) * 4;
                pfx = *(const float4*)&x[(rowbase + m) * 256 + kc + kq];
            }
#pragma unroll
            for (int i = 0; i < 2; ++i) {
                int f = t + 512 * i;
                int n = f >> 2;
                int k2 = (f & 3) * 4;
                pfw[i] = *(const float4*)&W1[(size_t)n * 256 + kc + k2];
            }
        }
#pragma unroll
        for (int kk = 0; kk < 16; ++kk) {
            unsigned long long av[4];
            const unsigned long long* xrow =
                (const unsigned long long*)&xst[cur][kk][m0];
#pragma unroll
            for (int p = 0; p < 4; ++p) av[p] = xrow[p];
            unsigned long long bv[8];
#pragma unroll
            for (int q = 0; q < 8; ++q) {
                float b = ws[cur][kk][l + 32 * q];
                bv[q] = f2pack(b, b);
            }
#pragma unroll
            for (int p = 0; p < 4; ++p)
#pragma unroll
                for (int q = 0; q < 8; ++q) ffma2(acc[p][q], av[p], bv[q]);
        }
        __syncthreads();
        if (ch < 15) {
            const int nxt = cur ^ 1;
            {
                int m  = t >> 2;
                int kq = (t & 3) * 4;
                xst[nxt][kq + 0][m] = pfx.x; xst[nxt][kq + 1][m] = pfx.y;
                xst[nxt][kq + 2][m] = pfx.z; xst[nxt][kq + 3][m] = pfx.w;
            }
#pragma unroll
            for (int i = 0; i < 2; ++i) {
                int f = t + 512 * i;
                int n = f >> 2;
                int k2 = (f & 3) * 4;
                ws[nxt][k2 + 0][n] = pfw[i].x; ws[nxt][k2 + 1][n] = pfw[i].y;
                ws[nxt][k2 + 2][n] = pfw[i].z; ws[nxt][k2 + 3][n] = pfw[i].w;
            }
            __syncthreads();
        }
    }

    // epilogue: +b1, store h1, column sums
    float b1v[8];
#pragma unroll
    for (int q = 0; q < 8; ++q) b1v[q] = b1[l + 32 * q];

    float cs[8], cq[8];
#pragma unroll
    for (int q = 0; q < 8; ++q) { cs[q] = 0.f; cq[q] = 0.f; }

#pragma unroll
    for (int p = 0; p < 4; ++p) {
        size_t r0 = (rowbase + m0 + 2 * p) * 256;
#pragma unroll
        for (int q = 0; q < 8; ++q) {
            float v0, v1;
            f2unpack(acc[p][q], v0, v1);
            v0 += b1v[q]; v1 += b1v[q];
            int n = l + 32 * q;
            g_h1[r0 + n]       = v0;
            g_h1[r0 + 256 + n] = v1;
            cs[q] += v0 + v1;
            cq[q] += v0 * v0 + v1 * v1;
        }
    }

#pragma unroll
    for (int q = 0; q < 8; ++q) {
        atomicAdd(&csum[l + 32 * q], cs[q]);
        atomicAdd(&csq[l + 32 * q],  cq[q]);
    }
    __syncthreads();
    if (t < 256) {
        atomicAdd(&g_sum[t],   csum[t]);
        atomicAdd(&g_sumsq[t], csq[t]);
    }
}

// ---------------- kernel B: finalize stats + fold small weights ------------------
__global__ void kB(const float* __restrict__ gamma, const float* __restrict__ beta,
                   const float* __restrict__ Wq, const float* __restrict__ bq,
                   const float* __restrict__ Wk, const float* __restrict__ bk,
                   const float* __restrict__ Wv, const float* __restrict__ bv,
                   const float* __restrict__ Wo, const float* __restrict__ bo,
                   const float* __restrict__ Wr, const float* __restrict__ br)
{
    __shared__ float qv[256], we[256], wrs[256];
    const int t = threadIdx.x;
    const float invN = 1.0f / (float)N_NODES;

    float mean = g_sum[t] * invN;
    float var  = g_sumsq[t] * invN - mean * mean;
    float rs   = rsqrtf(var + EPS_);
    float na   = gamma[t] * rs;
    g_na[t] = na;
    g_nd[t] = beta[t] - mean * na;

    float s = bq[t];
    for (int j = 0; j < 256; ++j) s += Wq[(size_t)t * 256 + j];
    qv[t]  = s;
    wrs[t] = Wr[t];
    __syncthreads();

    float e = 0.f;
    for (int j = 0; j < 256; ++j) e += wrs[j] * Wo[(size_t)j * 256 + t];
    we[t] = e;
    __syncthreads();

    for (int h = 0; h < 8; ++h) {
        float wk = 0.f, wv_ = 0.f;
        for (int d = 0; d < 32; ++d) {
            int c = h * 32 + d;
            wk  += qv[c] * Wk[(size_t)c * 256 + t];
            wv_ += we[c] * Wv[(size_t)c * 256 + t];
        }
        g_w16[h * 256 + t]       = wk * ATTN_SCALE;
        g_w16[(8 + h) * 256 + t] = wv_;
    }
    if (t < 8) {
        float bl = 0.f, bs = 0.f;
        for (int d = 0; d < 32; ++d) {
            int c = t * 32 + d;
            bl += qv[c] * bk[c];
            bs += we[c] * bv[c];
        }
        g_b16[t]     = bl * ATTN_SCALE;
        g_b16[8 + t] = bs;
    }
    if (t == 0) {
        float c0 = br[0];
        for (int j = 0; j < 256; ++j) c0 += wrs[j] * bo[j];
        g_c0 = c0;
    }
}

// ---------------- kernel C: per-group norm/relu/GEMM2/attn/out -------------------
// smem (floats):
#define YSTR_    130                              // y^T [k][m], padded
#define YS_OFF   0                                // 256*130 = 33280 (reused as h2[m][260])
#define H2STR_   260
#define WS2_OFF  33280                            // 2*16*256 = 8192
#define W16_OFF  (WS2_OFF + 8192)                 // 41472 ; 16 rows stride 260
#define W16STR_  260
#define LG_OFF   (W16_OFF + 16 * W16STR_)         // 45632 ; 128 rows stride 17
#define LGSTR_   17
#define HR_OFF   (LG_OFF + 128 * LGSTR_)          // 47808
#define NA_OFF   (HR_OFF + 8)                     // 47816 (16B aligned)
#define ND_OFF   (NA_OFF + 256)
#define SMC_FLOATS (ND_OFF + 256)                 // 48328 floats = 193312 B

__global__ void __launch_bounds__(512, 1)
kC(const float* __restrict__ W2, const float* __restrict__ b2, float* __restrict__ out)
{
    extern __shared__ float sm[];
    const int t = threadIdx.x;
    const int w = t >> 5, l = t & 31;
    const int m0 = w * 8;
    const int g = blockIdx.x;
    const float* h1 = g_h1 + (size_t)g * (128 * 256);

    if (t < 256) { sm[NA_OFF + t] = g_na[t]; sm[ND_OFF + t] = g_nd[t]; }
    __syncthreads();

    // phase 1: y = relu(na*h1 + nd) -> yst[k][m]; stage w16; W2 chunk 0
#pragma unroll
    for (int i = 0; i < 16; ++i) {
        int f  = t + 512 * i;
        int m  = f >> 6;
        int c4 = (f & 63) * 4;
        float4 v = *(const float4*)&h1[(size_t)m * 256 + c4];
        float4 a = *(const float4*)&sm[NA_OFF + c4];
        float4 d = *(const float4*)&sm[ND_OFF + c4];
        v.x = fmaxf(fmaf(v.x, a.x, d.x), 0.f);
        v.y = fmaxf(fmaf(v.y, a.y, d.y), 0.f);
        v.z = fmaxf(fmaf(v.z, a.z, d.z), 0.f);
        v.w = fmaxf(fmaf(v.w, a.w, d.w), 0.f);
        sm[YS_OFF + (c4 + 0) * YSTR_ + m] = v.x;
        sm[YS_OFF + (c4 + 1) * YSTR_ + m] = v.y;
        sm[YS_OFF + (c4 + 2) * YSTR_ + m] = v.z;
        sm[YS_OFF + (c4 + 3) * YSTR_ + m] = v.w;
    }
#pragma unroll
    for (int i = 0; i < 2; ++i) {
        int f  = t + 512 * i;
        int e  = f >> 6;
        int c4 = (f & 63) * 4;
        float4 v = *(const float4*)&g_w16[e * 256 + c4];
        *(float4*)&sm[W16_OFF + e * W16STR_ + c4] = v;
    }
#pragma unroll
    for (int i = 0; i < 2; ++i) {
        int f = t + 512 * i;
        int n = f >> 2;
        int k2 = (f & 3) * 4;
        float4 vw = *(const float4*)&W2[(size_t)n * 256 + k2];
        sm[WS2_OFF + (k2 + 0) * 256 + n] = vw.x;
        sm[WS2_OFF + (k2 + 1) * 256 + n] = vw.y;
        sm[WS2_OFF + (k2 + 2) * 256 + n] = vw.z;
        sm[WS2_OFF + (k2 + 3) * 256 + n] = vw.w;
    }
    __syncthreads();

    // GEMM2 main loop
    unsigned long long acc[4][8];
#pragma unroll
    for (int p = 0; p < 4; ++p)
#pragma unroll
        for (int q = 0; q < 8; ++q) acc[p][q] = 0ULL;

    float4 pfw[2];
    for (int ch = 0; ch < 16; ++ch) {
        const int cur = ch & 1;
        if (ch < 15) {
            const int kc = (ch + 1) * 16;
#pragma unroll
            for (int i = 0; i < 2; ++i) {
                int f = t + 512 * i;
                int n = f >> 2;
                int k2 = (f & 3) * 4;
                pfw[i] = *(const float4*)&W2[(size_t)n * 256 + kc + k2];
            }
        }
#pragma unroll
        for (int kk = 0; kk < 16; ++kk) {
            const int k = ch * 16 + kk;
            unsigned long long av[4];
            const unsigned long long* yrow =
                (const unsigned long long*)&sm[YS_OFF + k * YSTR_ + m0];
#pragma unroll
            for (int p = 0; p < 4; ++p) av[p] = yrow[p];
            unsigned long long bv[8];
#pragma unroll
            for (int q = 0; q < 8; ++q) {
                float b = sm[WS2_OFF + cur * 4096 + kk * 256 + l + 32 * q];
                bv[q] = f2pack(b, b);
            }
#pragma unroll
            for (int p = 0; p < 4; ++p)
#pragma unroll
                for (int q = 0; q < 8; ++q) ffma2(acc[p][q], av[p], bv[q]);
        }
        __syncthreads();
        if (ch < 15) {
            const int nxt = cur ^ 1;
#pragma unroll
            for (int i = 0; i < 2; ++i) {
                int f = t + 512 * i;
                int n = f >> 2;
                int k2 = (f & 3) * 4;
                sm[WS2_OFF + nxt * 4096 + (k2 + 0) * 256 + n] = pfw[i].x;
                sm[WS2_OFF + nxt * 4096 + (k2 + 1) * 256 + n] = pfw[i].y;
                sm[WS2_OFF + nxt * 4096 + (k2 + 2) * 256 + n] = pfw[i].z;
                sm[WS2_OFF + nxt * 4096 + (k2 + 3) * 256 + n] = pfw[i].w;
            }
            __syncthreads();
        }
    }

    // h2 = acc + b2 -> smem [m][260] (overwrites yst; all reads of y done)
    {
        float b2v[8];
#pragma unroll
        for (int q = 0; q < 8; ++q) b2v[q] = b2[l + 32 * q];
#pragma unroll
        for (int p = 0; p < 4; ++p) {
            int r0 = YS_OFF + (m0 + 2 * p) * H2STR_;
#pragma unroll
            for (int q = 0; q < 8; ++q) {
                float v0, v1;
                f2unpack(acc[p][q], v0, v1);
                int n = l + 32 * q;
                sm[r0 + n]          = v0 + b2v[q];
                sm[r0 + H2STR_ + n] = v1 + b2v[q];
            }
        }
    }
    __syncthreads();

    // phase 4: out16[n][e] = h2[n,:] . w16[e,:] + b16[e]  (packed f32x2)
    {
        const int e  = t & 15;
        const int nb = t >> 4;            // 0..31
        unsigned long long a2[4];
#pragma unroll
        for (int i = 0; i < 4; ++i) a2[i] = 0ULL;
        const float* wrow = &sm[W16_OFF + e * W16STR_];
#pragma unroll 4
        for (int k4 = 0; k4 < 64; ++k4) {
            ulonglong2 wv = *(const ulonglong2*)&wrow[k4 * 4];
#pragma unroll
            for (int i = 0; i < 4; ++i) {
                ulonglong2 hv =
                    *(const ulonglong2*)&sm[YS_OFF + (nb + 32 * i) * H2STR_ + k4 * 4];
                ffma2(a2[i], hv.x, wv.x);
                ffma2(a2[i], hv.y, wv.y);
            }
        }
        float bb = g_b16[e];
#pragma unroll
        for (int i = 0; i < 4; ++i) {
            float lo, hi;
            f2unpack(a2[i], lo, hi);
            sm[LG_OFF + (nb + 32 * i) * LGSTR_ + e] = lo + hi + bb;
        }
    }
    __syncthreads();

    // phase 5: per-head softmax over 128 nodes + weighted sum
    {
        const int wh   = t >> 5;
        const int lane = t & 31;
        if (wh < 8) {
            float lv[4];
#pragma unroll
            for (int i = 0; i < 4; ++i)
                lv[i] = sm[LG_OFF + (lane + 32 * i) * LGSTR_ + wh];
            float m = fmaxf(fmaxf(lv[0], lv[1]), fmaxf(lv[2], lv[3]));
#pragma unroll
            for (int o = 16; o > 0; o >>= 1)
                m = fmaxf(m, __shfl_xor_sync(0xffffffffu, m, o));
            float ps = 0.f, pv = 0.f;
#pragma unroll
            for (int i = 0; i < 4; ++i) {
                float p = __expf(lv[i] - m);
                ps += p;
                pv += p * sm[LG_OFF + (lane + 32 * i) * LGSTR_ + 8 + wh];
            }
#pragma unroll
            for (int o = 16; o > 0; o >>= 1) {
                ps += __shfl_xor_sync(0xffffffffu, ps, o);
                pv += __shfl_xor_sync(0xffffffffu, pv, o);
            }
            if (lane == 0) sm[HR_OFF + wh] = pv / ps;
        }
    }
    __syncthreads();
    if (t == 0) {
        float r = g_c0;
#pragma unroll
        for (int h = 0; h < 8; ++h) r += sm[HR_OFF + h];
        out[g] = tanhf(r);
    }
}

// ---------------- launch ---------------------------------------------------------
extern "C" void kernel_launch(void* const* d_in, const int* in_sizes, int n_in,
                              void* d_out, int out_size)
{
    const int base = n_in - 16;
    const float* x     = (const float*)d_in[0];
    const float* W1    = (const float*)d_in[base + 0];
    const float* b1    = (const float*)d_in[base + 1];
    const float* gamma = (const float*)d_in[base + 2];
    const float* beta  = (const float*)d_in[base + 3];
    const float* W2    = (const float*)d_in[base + 4];
    const float* b2    = (const float*)d_in[base + 5];
    const float* Wq    = (const float*)d_in[base + 6];
    const float* bq    = (const float*)d_in[base + 7];
    const float* Wk    = (const float*)d_in[base + 8];
    const float* bk    = (const float*)d_in[base + 9];
    const float* Wv    = (const float*)d_in[base + 10];
    const float* bv    = (const float*)d_in[base + 11];
    const float* Wo    = (const float*)d_in[base + 12];
    const float* bo    = (const float*)d_in[base + 13];
    const float* Wr    = (const float*)d_in[base + 14];
    const float* br    = (const float*)d_in[base + 15];

    kZero<<<1, 256>>>();
    kA<<<B_GRAPHS, 512>>>(x, W1, b1);
    kB<<<1, 256>>>(gamma, beta, Wq, bq, Wk, bk, Wv, bv, Wo, bo, Wr, br);

    const size_t shc = (size_t)SMC_FLOATS * sizeof(float);
    cudaFuncSetAttribute((const void*)kC,
                         cudaFuncAttributeMaxDynamicSharedMemorySize, (int)shc);
    kC<<<B_GRAPHS, 512, shc>>>(W2, b2, (float*)d_out);
}

// round 16
// speedup vs baseline: 2.3900x; 1.4751x over previous
#include <cuda_runtime.h>
#include <math.h>

#define C_DIM    256
#define H_DIM    8
#define B_GRAPHS 2048
#define NPG_     128
#define N_NODES  (B_GRAPHS * NPG_)
#define EPS_     1e-5f
#define ATTN_SCALE 0.17677669529663687f   /* 1/sqrt(32) */

// ---------------- scratch (device globals; no allocation allowed) ----------------
__device__ float g_h1[(size_t)N_NODES * C_DIM];   // h1 = x@W1^T + b1
__device__ float g_sum[C_DIM];
__device__ float g_sumsq[C_DIM];
__device__ float g_na[C_DIM];          // gamma*rsqrt(var+eps)
__device__ float g_nd[C_DIM];          // beta - mean*na
__device__ float g_w16eff[16 * C_DIM]; // folded (w16 @ W2): e<8 logits, e>=8 values
__device__ float g_b16eff[16];         // folded b16 + w16.b2
__device__ float g_c0;                 // Wr.bo + br

// ---------------- f32x2 packed-FMA helpers --------------------------------------
__device__ __forceinline__ unsigned long long f2pack(float lo, float hi) {
    unsigned long long r;
    asm("mov.b64 %0, {%1, %2};" : "=l"(r) : "f"(lo), "f"(hi));
    return r;
}
__device__ __forceinline__ void ffma2(unsigned long long& d,
                                      unsigned long long a, unsigned long long b) {
    asm("fma.rn.f32x2 %0, %1, %2, %0;" : "+l"(d) : "l"(a), "l"(b));
}
__device__ __forceinline__ void f2unpack(unsigned long long v, float& lo, float& hi) {
    asm("mov.b64 {%0, %1}, %2;" : "=f"(lo), "=f"(hi) : "l"(v));
}

// ---------------- kernel Z: zero stats ------------------------------------------
__global__ void kZero() {
    int t = threadIdx.x;
    if (t < C_DIM) { g_sum[t] = 0.f; g_sumsq[t] = 0.f; }
}

// ---------------- kernel A: h1 = x @ W1^T + b1, + column sum/sumsq ---------------
// (unchanged from the 1607us passing version)
__global__ void __launch_bounds__(512, 1)
kA(const float* __restrict__ x, const float* __restrict__ W1, const float* __restrict__ b1)
{
    __shared__ __align__(16) float xst[2][16][128];   // [k][m]
    __shared__ __align__(16) float ws[2][16][256];    // [k][n]
    __shared__ float csum[256];
    __shared__ float csq[256];

    const int t = threadIdx.x;
    const int w = t >> 5, l = t & 31;
    const int m0 = w * 8;
    const size_t rowbase = (size_t)blockIdx.x * 128;

    if (t < 256) { csum[t] = 0.f; csq[t] = 0.f; }

    unsigned long long acc[4][8];
#pragma unroll
    for (int p = 0; p < 4; ++p)
#pragma unroll
        for (int q = 0; q < 8; ++q) acc[p][q] = 0ULL;

    // prologue: chunk 0
    {
        int m  = t >> 2;
        int kq = (t & 3) * 4;
        float4 vx = *(const float4*)&x[(rowbase + m) * 256 + kq];
        xst[0][kq + 0][m] = vx.x; xst[0][kq + 1][m] = vx.y;
        xst[0][kq + 2][m] = vx.z; xst[0][kq + 3][m] = vx.w;
#pragma unroll
        for (int i = 0; i < 2; ++i) {
            int f = t + 512 * i;
            int n = f >> 2;
            int k2 = (f & 3) * 4;
            float4 vw = *(const float4*)&W1[(size_t)n * 256 + k2];
            ws[0][k2 + 0][n] = vw.x; ws[0][k2 + 1][n] = vw.y;
            ws[0][k2 + 2][n] = vw.z; ws[0][k2 + 3][n] = vw.w;
        }
    }
    __syncthreads();

    float4 pfx;
    float4 pfw[2];
    for (int ch = 0; ch < 16; ++ch) {
        const int cur = ch & 1;
        if (ch < 15) {
            const int kc = (ch + 1) * 16;
            {
                int m  = t >> 2;
                int kq = (t & 3) * 4;
                pfx = *(const float4*)&x[(rowbase + m) * 256 + kc + kq];
            }
#pragma unroll
            for (int i = 0; i < 2; ++i) {
                int f = t + 512 * i;
                int n = f >> 2;
                int k2 = (f & 3) * 4;
                pfw[i] = *(const float4*)&W1[(size_t)n * 256 + kc + k2];
            }
        }
#pragma unroll
        for (int kk = 0; kk < 16; ++kk) {
            unsigned long long av[4];
            const unsigned long long* xrow =
                (const unsigned long long*)&xst[cur][kk][m0];
#pragma unroll
            for (int p = 0; p < 4; ++p) av[p] = xrow[p];
            unsigned long long bv[8];
#pragma unroll
            for (int q = 0; q < 8; ++q) {
                float b = ws[cur][kk][l + 32 * q];
                bv[q] = f2pack(b, b);
            }
#pragma unroll
            for (int p = 0; p < 4; ++p)
#pragma unroll
                for (int q = 0; q < 8; ++q) ffma2(acc[p][q], av[p], bv[q]);
        }
        __syncthreads();
        if (ch < 15) {
            const int nxt = cur ^ 1;
            {
                int m  = t >> 2;
                int kq = (t & 3) * 4;
                xst[nxt][kq + 0][m] = pfx.x; xst[nxt][kq + 1][m] = pfx.y;
                xst[nxt][kq + 2][m] = pfx.z; xst[nxt][kq + 3][m] = pfx.w;
            }
#pragma unroll
            for (int i = 0; i < 2; ++i) {
                int f = t + 512 * i;
                int n = f >> 2;
                int k2 = (f & 3) * 4;
                ws[nxt][k2 + 0][n] = pfw[i].x; ws[nxt][k2 + 1][n] = pfw[i].y;
                ws[nxt][k2 + 2][n] = pfw[i].z; ws[nxt][k2 + 3][n] = pfw[i].w;
            }
            __syncthreads();
        }
    }

    // epilogue: +b1, store h1, column sums
    float b1v[8];
#pragma unroll
    for (int q = 0; q < 8; ++q) b1v[q] = b1[l + 32 * q];

    float cs[8], cq[8];
#pragma unroll
    for (int q = 0; q < 8; ++q) { cs[q] = 0.f; cq[q] = 0.f; }

#pragma unroll
    for (int p = 0; p < 4; ++p) {
        size_t r0 = (rowbase + m0 + 2 * p) * 256;
#pragma unroll
        for (int q = 0; q < 8; ++q) {
            float v0, v1;
            f2unpack(acc[p][q], v0, v1);
            v0 += b1v[q]; v1 += b1v[q];
            int n = l + 32 * q;
            g_h1[r0 + n]       = v0;
            g_h1[r0 + 256 + n] = v1;
            cs[q] += v0 + v1;
            cq[q] += v0 * v0 + v1 * v1;
        }
    }

#pragma unroll
    for (int q = 0; q < 8; ++q) {
        atomicAdd(&csum[l + 32 * q], cs[q]);
        atomicAdd(&csq[l + 32 * q],  cq[q]);
    }
    __syncthreads();
    if (t < 256) {
        atomicAdd(&g_sum[t],   csum[t]);
        atomicAdd(&g_sumsq[t], csq[t]);
    }
}

// ---------------- kernel B: finalize BN params ------------------------------------
__global__ void kB(const float* __restrict__ gamma, const float* __restrict__ beta) {
    const int t = threadIdx.x;
    const float invN = 1.0f / (float)N_NODES;
    float m   = g_sum[t] * invN;
    float var = g_sumsq[t] * invN - m * m;
    float na  = gamma[t] * rsqrtf(var + EPS_);
    g_na[t] = na;
    g_nd[t] = beta[t] - m * na;
}

// ---------------- kFold: fold q/Wk/Wv/Wo/Wr/W2/b2 into 16 effective vectors -------
// 1 block, 256 threads.
__global__ void kFold(const float* __restrict__ Wq, const float* __restrict__ bq,
                      const float* __restrict__ Wk, const float* __restrict__ bk,
                      const float* __restrict__ Wv, const float* __restrict__ bv,
                      const float* __restrict__ Wo, const float* __restrict__ bo,
                      const float* __restrict__ Wr, const float* __restrict__ br,
                      const float* __restrict__ W2, const float* __restrict__ b2) {
    __shared__ float qv[256], we[256], wrs[256], s16[16][256], sb16[16];
    const int t = threadIdx.x;

    // qh = rowsum(Wq) + bq   (q == ones)
    float s = bq[t];
    for (int j = 0; j < 256; ++j) s += Wq[(size_t)t * 256 + j];
    qv[t] = s;
    wrs[t] = Wr[t];
    __syncthreads();

    // weff = Wr @ Wo
    float e = 0.f;
    for (int j = 0; j < 256; ++j) e += wrs[j] * Wo[(size_t)j * 256 + t];
    we[t] = e;
    __syncthreads();

    // w16 over h2-space (prescaled)
    for (int h = 0; h < 8; ++h) {
        float wk = 0.f, wv_ = 0.f;
        for (int d = 0; d < 32; ++d) {
            int c = h * 32 + d;
            wk  += qv[c] * Wk[(size_t)c * 256 + t];
            wv_ += we[c] * Wv[(size_t)c * 256 + t];
        }
        s16[h][t]     = wk * ATTN_SCALE;
        s16[8 + h][t] = wv_;
    }
    if (t < 8) {
        float bl = 0.f, bs = 0.f;
        for (int d = 0; d < 32; ++d) {
            int c = t * 32 + d;
            bl += qv[c] * bk[c];
            bs += we[c] * bv[c];
        }
        sb16[t]     = bl * ATTN_SCALE;
        sb16[8 + t] = bs;
    }
    if (t == 0) {
        float c0 = br[0];
        for (int j = 0; j < 256; ++j) c0 += wrs[j] * bo[j];
        g_c0 = c0;
    }
    __syncthreads();

    // fold through W2: w16eff[e,t] = sum_j s16[e][j] * W2[j,t]  (W2 row-major [n][k])
    float acc[16];
#pragma unroll
    for (int ei = 0; ei < 16; ++ei) acc[ei] = 0.f;
    for (int j = 0; j < 256; ++j) {
        float w2v = W2[(size_t)j * 256 + t];
#pragma unroll
        for (int ei = 0; ei < 16; ++ei) acc[ei] += s16[ei][j] * w2v;
    }
#pragma unroll
    for (int ei = 0; ei < 16; ++ei) g_w16eff[ei * 256 + t] = acc[ei];
    if (t < 16) {
        float bb = sb16[t];
        for (int j = 0; j < 256; ++j) bb += s16[t][j] * b2[j];
        g_b16eff[t] = bb;
    }
}

// ---------------- kernel C: norm/relu + 16-dot + softmax + tanh (no GEMM2) --------
#define YC_   0                       // y [128][260]
#define W16C_ 33280                   // 16 rows stride 260
#define LGC_  (W16C_ + 16 * 260)      // 37440 ; 128 rows stride 17
#define HRC_  (LGC_ + 128 * 17)       // 39616
#define NAC_  (HRC_ + 8)              // 39624
#define NDC_  (NAC_ + 256)            // 39880
#define SMC_FLOATS (NDC_ + 256)       // 40136 floats = 160544 B

__global__ void __launch_bounds__(512, 1)
kC(float* __restrict__ out)
{
    extern __shared__ float sm[];
    const int t = threadIdx.x;
    const int g = blockIdx.x;
    const float* h1 = g_h1 + (size_t)g * (128 * 256);

    if (t < 256) { sm[NAC_ + t] = g_na[t]; sm[NDC_ + t] = g_nd[t]; }
    __syncthreads();

    // phase 1: y = relu(na*h1 + nd) -> [n][260]; stage w16_eff
#pragma unroll
    for (int i = 0; i < 16; ++i) {
        int f  = t + 512 * i;
        int m  = f >> 6;
        int c4 = (f & 63) * 4;
        float4 v = *(const float4*)&h1[(size_t)m * 256 + c4];
        float4 a = *(const float4*)&sm[NAC_ + c4];
        float4 d = *(const float4*)&sm[NDC_ + c4];
        v.x = fmaxf(fmaf(v.x, a.x, d.x), 0.f);
        v.y = fmaxf(fmaf(v.y, a.y, d.y), 0.f);
        v.z = fmaxf(fmaf(v.z, a.z, d.z), 0.f);
        v.w = fmaxf(fmaf(v.w, a.w, d.w), 0.f);
        *(float4*)&sm[YC_ + m * 260 + c4] = v;
    }
#pragma unroll
    for (int i = 0; i < 2; ++i) {
        int f  = t + 512 * i;
        int e  = f >> 6;
        int c4 = (f & 63) * 4;
        float4 v = *(const float4*)&g_w16eff[e * 256 + c4];
        *(float4*)&sm[W16C_ + e * 260 + c4] = v;
    }
    __syncthreads();

    // phase 2: out16[n][e] = y[n,:] . w16_eff[e,:] + b16_eff[e]   (f32x2)
    // thread (e = t&15, nb = t>>4): y loads broadcast across 16 lanes.
    {
        const int e  = t & 15;
        const int nb = t >> 4;            // 0..31
        unsigned long long a2[4];
#pragma unroll
        for (int i = 0; i < 4; ++i) a2[i] = 0ULL;
        const float* wrow = &sm[W16C_ + e * 260];
#pragma unroll 4
        for (int k4 = 0; k4 < 64; ++k4) {
            ulonglong2 wv = *(const ulonglong2*)&wrow[k4 * 4];
#pragma unroll
            for (int i = 0; i < 4; ++i) {
                ulonglong2 hv = *(const ulonglong2*)&sm[YC_ + (nb + 32 * i) * 260 + k4 * 4];
                ffma2(a2[i], hv.x, wv.x);
                ffma2(a2[i], hv.y, wv.y);
            }
        }
        float bb = g_b16eff[e];
#pragma unroll
        for (int i = 0; i < 4; ++i) {
            float lo, hi;
            f2unpack(a2[i], lo, hi);
            sm[LGC_ + (nb + 32 * i) * 17 + e] = lo + hi + bb;
        }
    }
    __syncthreads();

    // phase 3: per-head softmax over 128 nodes + weighted sum of values
    {
        const int wh   = t >> 5;
        const int lane = t & 31;
        if (wh < 8) {
            float lv[4];
#pragma unroll
            for (int i = 0; i < 4; ++i)
                lv[i] = sm[LGC_ + (lane + 32 * i) * 17 + wh];
            float m = fmaxf(fmaxf(lv[0], lv[1]), fmaxf(lv[2], lv[3]));
#pragma unroll
            for (int o = 16; o > 0; o >>= 1)
                m = fmaxf(m, __shfl_xor_sync(0xffffffffu, m, o));
            float ps = 0.f, pv = 0.f;
#pragma unroll
            for (int i = 0; i < 4; ++i) {
                float p = __expf(lv[i] - m);
                ps += p;
                pv += p * sm[LGC_ + (lane + 32 * i) * 17 + 8 + wh];
            }
#pragma unroll
            for (int o = 16; o > 0; o >>= 1) {
                ps += __shfl_xor_sync(0xffffffffu, ps, o);
                pv += __shfl_xor_sync(0xffffffffu, pv, o);
            }
            if (lane == 0) sm[HRC_ + wh] = pv / ps;
        }
    }
    __syncthreads();
    if (t == 0) {
        float r = g_c0;
#pragma unroll
        for (int h = 0; h < 8; ++h) r += sm[HRC_ + h];
        out[g] = tanhf(r);
    }
}

// ---------------- launch -----------------------------------------------------------
extern "C" void kernel_launch(void* const* d_in, const int* in_sizes, int n_in,
                              void* d_out, int out_size)
{
    const int base = n_in - 16;
    const float* x     = (const float*)d_in[0];
    const float* W1    = (const float*)d_in[base + 0];
    const float* b1    = (const float*)d_in[base + 1];
    const float* gamma = (const float*)d_in[base + 2];
    const float* beta  = (const float*)d_in[base + 3];
    const float* W2    = (const float*)d_in[base + 4];
    const float* b2    = (const float*)d_in[base + 5];
    const float* Wq    = (const float*)d_in[base + 6];
    const float* bq    = (const float*)d_in[base + 7];
    const float* Wk    = (const float*)d_in[base + 8];
    const float* bk    = (const float*)d_in[base + 9];
    const float* Wv    = (const float*)d_in[base + 10];
    const float* bv    = (const float*)d_in[base + 11];
    const float* Wo    = (const float*)d_in[base + 12];
    const float* bo    = (const float*)d_in[base + 13];
    const float* Wr    = (const float*)d_in[base + 14];
    const float* br    = (const float*)d_in[base + 15];

    kZero<<<1, 256>>>();
    kA<<<B_GRAPHS, 512>>>(x, W1, b1);
    kB<<<1, 256>>>(gamma, beta);
    kFold<<<1, 256>>>(Wq, bq, Wk, bk, Wv, bv, Wo, bo, Wr, br, W2, b2);

    const size_t shc = (size_t)SMC_FLOATS * sizeof(float);
    cudaFuncSetAttribute((const void*)kC,
                         cudaFuncAttributeMaxDynamicSharedMemorySize, (int)shc);
    kC<<<B_GRAPHS, 512, shc>>>((float*)d_out);
}